// round 17
// baseline (speedup 1.0000x reference)
#include <cuda_runtime.h>
#include <cuda_bf16.h>
#include <math.h>
#include <stdint.h>

#define BATCH 4
#define SEQ   4096
#define HID   1024
#define FF    4096
#define NROWS (BATCH*SEQ)          // 16384
#define TOT   (NROWS*HID)          // 16777216

// ---------------- scratch (static device arrays; no allocation allowed) ----
__device__ float  g_fr[TOT];                 // x_ft
__device__ float  g_fi[TOT];                 // fft imag; then tf32-rounded h; then y
__device__ float  g_h [TOT];                 // h = LN1(x + x_ft), exact (residual)
__device__ float  g_act[(size_t)NROWS*FF];   // gelu(h@w1+b1), tf32-rounded
__device__ float  g_w1t[(size_t)HID*FF];     // [FF][HID] K-major, tf32-rounded
__device__ float  g_w2t[(size_t)HID*FF];     // [HID][FF] K-major, tf32-rounded
__device__ float2 g_tw[2048];                // e^{-2*pi*i*j/4096}

// ============================================================================
// PTX helpers (arch-generic: mma.sync tf32 + cp.async + ldmatrix)
// ============================================================================
__device__ __forceinline__ uint32_t smem_u32(const void* p) {
    uint32_t a;
    asm("{ .reg .u64 t; cvta.to.shared.u64 t, %1; cvt.u32.u64 %0, t; }"
        : "=r"(a) : "l"(p));
    return a;
}
// round-to-nearest fp32 -> tf32 (result is fp32 bit-pattern, low 13 bits 0)
__device__ __forceinline__ float tf32r(float f) {
    uint32_t r;
    asm("cvt.rna.tf32.f32 %0, %1;" : "=r"(r) : "f"(f));
    return __uint_as_float(r);
}
__device__ __forceinline__ void mma16808(float* d,
                                         uint32_t a0, uint32_t a1, uint32_t a2, uint32_t a3,
                                         uint32_t b0, uint32_t b1) {
    asm volatile(
        "mma.sync.aligned.m16n8k8.row.col.f32.tf32.tf32.f32 "
        "{%0,%1,%2,%3}, {%4,%5,%6,%7}, {%8,%9}, {%0,%1,%2,%3};"
        : "+f"(d[0]), "+f"(d[1]), "+f"(d[2]), "+f"(d[3])
        : "r"(a0), "r"(a1), "r"(a2), "r"(a3), "r"(b0), "r"(b1));
}
#define LDM_X4(r0, r1, r2, r3, addr) \
    asm volatile("ldmatrix.sync.aligned.m8n8.x4.shared.b16 {%0,%1,%2,%3}, [%4];" \
        : "=r"(r0), "=r"(r1), "=r"(r2), "=r"(r3) : "r"(addr))
#define CP_ASYNC16(dst_u32, src_ptr) \
    asm volatile("cp.async.cg.shared.global [%0], [%1], 16;" \
        :: "r"(dst_u32), "l"(src_ptr))
#define CP_COMMIT() asm volatile("cp.async.commit_group;" ::: "memory")
#define CP_WAIT(n)  asm volatile("cp.async.wait_group %0;" :: "n"(n) : "memory")

__device__ __forceinline__ float2 cmul(float2 a, float2 b) {
    return make_float2(a.x * b.x - a.y * b.y, a.y * b.x + a.x * b.y);
}

// ---------------- twiddle init ---------------------------------------------
__global__ void twiddle_init_kernel() {
    int j = blockIdx.x * blockDim.x + threadIdx.x;
    if (j < 2048) {
        float ang = -6.283185307179586f * (float)j / 4096.0f;
        float s, c;
        sincosf(ang, &s, &c);
        g_tw[j] = make_float2(c, s);
    }
}

// ---------------- weight transpose + tf32 round -----------------------------
// W: [K][N] fp32 row-major  ->  T: [N][K] tf32-rounded fp32 (K-major operand)
__global__ void transpose_round_kernel(const float* __restrict__ W,
                                       float* __restrict__ T,
                                       int K, int N) {
    __shared__ float t[32][33];
    const int n = blockIdx.x * 32 + threadIdx.x;
    const int k0 = blockIdx.y * 32;
    #pragma unroll
    for (int j = 0; j < 32; j += 8)
        t[threadIdx.y + j][threadIdx.x] = W[(size_t)(k0 + threadIdx.y + j) * N + n];
    __syncthreads();
    const int k = k0 + threadIdx.x;
    #pragma unroll
    for (int j = 0; j < 32; j += 8) {
        size_t o = (size_t)(blockIdx.x * 32 + threadIdx.y + j) * K + k;
        T[o] = tf32r(t[threadIdx.x][threadIdx.y + j]);
    }
}

// ---------------- FFT over hidden dim (N=1024), radix-4, one row/block -----
#define PAD16(i) ((i) + ((i) >> 4))
#define HID_SMEM_ELEMS (1024 + 64)
__global__ void fft_hidden_kernel(const float* __restrict__ x) {
    __shared__ float2 sc[HID_SMEM_ELEMS];
    const int row = blockIdx.x;
    const float* xp = x + (size_t)row * HID;
    for (int i = threadIdx.x; i < 1024; i += 256) {
        int r = __brev((unsigned)i) >> 22;
        sc[PAD16(r)] = make_float2(xp[i], 0.f);
    }
    __syncthreads();
    #pragma unroll
    for (int p = 0; p < 5; p++) {
        const int s = 2 * p + 1;
        const int q = 1 << (s - 1);
        const int j = threadIdx.x;                 // 256 butterflies
        const int k  = j & (q - 1);
        const int i0 = ((j >> (s - 1)) << (s + 1)) + k;
        const float2 w1 = g_tw[k << (12 - s)];
        const float2 w2 = g_tw[k << (11 - s)];
        float2 a = sc[PAD16(i0)];
        float2 b = sc[PAD16(i0 + q)];
        float2 c = sc[PAD16(i0 + 2 * q)];
        float2 d = sc[PAD16(i0 + 3 * q)];
        float2 wb = cmul(w1, b), wd = cmul(w1, d);
        float2 A = make_float2(a.x + wb.x, a.y + wb.y);
        float2 B = make_float2(a.x - wb.x, a.y - wb.y);
        float2 C = make_float2(c.x + wd.x, c.y + wd.y);
        float2 D = make_float2(c.x - wd.x, c.y - wd.y);
        float2 wC = cmul(w2, C), wD = cmul(w2, D);
        sc[PAD16(i0)]         = make_float2(A.x + wC.x, A.y + wC.y);
        sc[PAD16(i0 + 2 * q)] = make_float2(A.x - wC.x, A.y - wC.y);
        sc[PAD16(i0 + q)]     = make_float2(B.x + wD.y, B.y - wD.x);  // -i*wD
        sc[PAD16(i0 + 3 * q)] = make_float2(B.x - wD.y, B.y + wD.x);
        __syncthreads();
    }
    float* fr = g_fr + (size_t)row * HID;
    float* fi = g_fi + (size_t)row * HID;
    for (int i = threadIdx.x; i < 1024; i += 256) {
        float2 v = sc[PAD16(i)];
        fr[i] = v.x;
        fi[i] = v.y;
    }
}

// ---------------- FFT over seq dim (N=4096), radix-4, 4 columns/block ------
#define SEQ_COL_ELEMS (4096 + 256)                  // padded column stride
#define SEQ_SMEM (4 * SEQ_COL_ELEMS * (int)sizeof(float2))   // 139264 B
__global__ void fft_seq_kernel() {
    extern __shared__ float2 sc4[];                 // [4][SEQ_COL_ELEMS]
    const int col0 = blockIdx.x * 4;
    const int b    = col0 >> 10;
    const int h0   = col0 & 1023;
    const size_t base = (size_t)b * SEQ * HID + h0;

    for (int i = threadIdx.x; i < 4096; i += 512) {
        int r = PAD16(__brev((unsigned)i) >> 20);
        float4 vr = *(const float4*)(g_fr + base + (size_t)i * HID);
        float4 vi = *(const float4*)(g_fi + base + (size_t)i * HID);
        sc4[0 * SEQ_COL_ELEMS + r] = make_float2(vr.x, vi.x);
        sc4[1 * SEQ_COL_ELEMS + r] = make_float2(vr.y, vi.y);
        sc4[2 * SEQ_COL_ELEMS + r] = make_float2(vr.z, vi.z);
        sc4[3 * SEQ_COL_ELEMS + r] = make_float2(vr.w, vi.w);
    }
    __syncthreads();

    {
        const int c  = threadIdx.x >> 7;            // 0..3, warp-uniform
        const int jb = threadIdx.x & 127;
        float2* cs = sc4 + c * SEQ_COL_ELEMS;
        #pragma unroll
        for (int p = 0; p < 6; p++) {
            const int s = 2 * p + 1;
            const int q = 1 << (s - 1);
            #pragma unroll
            for (int j = jb; j < 1024; j += 128) {  // 1024 butterflies/column
                const int k  = j & (q - 1);
                const int i0 = ((j >> (s - 1)) << (s + 1)) + k;
                const float2 w1 = g_tw[k << (12 - s)];
                const float2 w2 = g_tw[k << (11 - s)];
                float2 a = cs[PAD16(i0)];
                float2 bb = cs[PAD16(i0 + q)];
                float2 cc = cs[PAD16(i0 + 2 * q)];
                float2 d = cs[PAD16(i0 + 3 * q)];
                float2 wb = cmul(w1, bb), wd = cmul(w1, d);
                float2 A = make_float2(a.x + wb.x, a.y + wb.y);
                float2 B = make_float2(a.x - wb.x, a.y - wb.y);
                float2 C = make_float2(cc.x + wd.x, cc.y + wd.y);
                float2 D = make_float2(cc.x - wd.x, cc.y - wd.y);
                float2 wC = cmul(w2, C), wD = cmul(w2, D);
                cs[PAD16(i0)]         = make_float2(A.x + wC.x, A.y + wC.y);
                cs[PAD16(i0 + 2 * q)] = make_float2(A.x - wC.x, A.y - wC.y);
                cs[PAD16(i0 + q)]     = make_float2(B.x + wD.y, B.y - wD.x);
                cs[PAD16(i0 + 3 * q)] = make_float2(B.x - wD.y, B.y + wD.x);
            }
            __syncthreads();
        }
    }

    for (int i = threadIdx.x; i < 4096; i += 512) {
        int si = PAD16(i);
        float4 o = make_float4(sc4[0 * SEQ_COL_ELEMS + si].x,
                               sc4[1 * SEQ_COL_ELEMS + si].x,
                               sc4[2 * SEQ_COL_ELEMS + si].x,
                               sc4[3 * SEQ_COL_ELEMS + si].x);
        *(float4*)(g_fr + base + (size_t)i * HID) = o;   // real part only
    }
}

// ---------------- out = LayerNorm(a [+ b]); optional tf32-rounded copy -----
__global__ void add_ln_kernel(const float* __restrict__ a,
                              const float* __restrict__ badd,
                              const float* __restrict__ gamma,
                              const float* __restrict__ beta,
                              float* __restrict__ out,
                              float* __restrict__ orou) {
    const int row = blockIdx.x;
    const int tid = threadIdx.x;
    const float4* a4 = (const float4*)(a + (size_t)row * HID);
    float4 v = a4[tid];
    if (badd) {
        const float4* b4 = (const float4*)(badd + (size_t)row * HID);
        float4 w = b4[tid];
        v.x += w.x; v.y += w.y; v.z += w.z; v.w += w.w;
    }
    float sum = v.x + v.y + v.z + v.w;
    float sq  = v.x*v.x + v.y*v.y + v.z*v.z + v.w*v.w;
    __shared__ float s1[8], s2[8];
    #pragma unroll
    for (int o = 16; o > 0; o >>= 1) {
        sum += __shfl_xor_sync(0xffffffffu, sum, o);
        sq  += __shfl_xor_sync(0xffffffffu, sq,  o);
    }
    const int warp = tid >> 5, lane = tid & 31;
    if (lane == 0) { s1[warp] = sum; s2[warp] = sq; }
    __syncthreads();
    if (warp == 0) {
        float a1 = (lane < 8) ? s1[lane] : 0.f;
        float a2 = (lane < 8) ? s2[lane] : 0.f;
        #pragma unroll
        for (int o = 4; o > 0; o >>= 1) {
            a1 += __shfl_xor_sync(0xffffffffu, a1, o);
            a2 += __shfl_xor_sync(0xffffffffu, a2, o);
        }
        if (lane == 0) { s1[0] = a1; s2[0] = a2; }
    }
    __syncthreads();
    const float mu  = s1[0] * (1.0f / 1024.0f);
    const float var = s2[0] * (1.0f / 1024.0f) - mu * mu;
    const float inv = rsqrtf(var + 1e-5f);
    const float4 g  = ((const float4*)gamma)[tid];
    const float4 bt = ((const float4*)beta)[tid];
    float o[4];
    o[0] = (v.x - mu) * inv * g.x + bt.x;
    o[1] = (v.y - mu) * inv * g.y + bt.y;
    o[2] = (v.z - mu) * inv * g.z + bt.z;
    o[3] = (v.w - mu) * inv * g.w + bt.w;
    ((float4*)(out + (size_t)row * HID))[tid] = *(float4*)o;
    if (orou) {
        float r[4];
        #pragma unroll
        for (int e = 0; e < 4; e++) r[e] = tf32r(o[e]);
        ((float4*)(orou + (size_t)row * HID))[tid] = *(float4*)r;
    }
}

// ============================================================================
// Single-pass TF32 GEMM on mma.sync.m16n8k8.  CTA tile 128x128, BK=32,
// 8 warps, warp tile 64x32.  3-stage cp.async pipeline, one barrier/chunk,
// 2 CTAs/SM.  Inputs are tf32-pre-rounded fp32; HW reads them as tf32.
// GELU=1: C = tf32r(gelu(A@B + bias)) -> fp32.   GELU=0: C = A@B+bias+res.
// ============================================================================
#define LDKF 36                        // padded row stride (floats), 144 B
#define BUF_BYTES (128 * LDKF * 4)     // 18432 B
#define STAGES 3
#define GEMM_SMEM (STAGES * 2 * BUF_BYTES)   // 110592 B

template<int GELU>
__global__ void __launch_bounds__(256, 2)
tf32_gemm_kernel(const float* __restrict__ A,
                 const float* __restrict__ B,
                 const float* __restrict__ bias,
                 const float* __restrict__ res,
                 float* __restrict__ Of,
                 int M, int N, int K)
{
    extern __shared__ float smem[];        // [STAGES][2 bufs][128][LDKF]
    const int tid  = threadIdx.x;
    const int wid  = tid >> 5;
    const int lane = tid & 31;
    const int wm = wid >> 2;        // 0..1
    const int wn = wid & 3;         // 0..3
    const int g  = lane >> 2;       // 0..7
    const int tg = lane & 3;        // 0..3
    const int m0 = blockIdx.y * 128;
    const int n0 = blockIdx.x * 128;

    // cp.async mapping: chunk-major for conflict-free phases
    const int rowc  = tid & 63;            // row within 64-half
    const int cbase = tid >> 6;            // chunk 0..3 (of 8 4-float chunks)
    const uint32_t sbase = smem_u32(smem);

    // ldmatrix A: x4 tiles (rows g/g+8) x (float cols 0-3 / 4-7), +ks*8 floats
    const int arow = wm * 64 + (lane & 7) + ((lane >> 3) & 1) * 8;  // +mf*16
    const int acolf = ((lane >> 4) & 1) * 4;
    const uint32_t aoff = (uint32_t)(arow * LDKF + acolf) * 4;
    // ldmatrix B: x4 covering nf-pair (rows nf / nf+1 groups) x (k 0-3 / 4-7)
    const int brow = wn * 32 + (lane & 7) + ((lane >> 4) & 1) * 8;  // +pair*16
    const int bcolf = ((lane >> 3) & 1) * 4;
    const uint32_t boff = (uint32_t)(brow * LDKF + bcolf) * 4;

    float acc[4][4][4];
    #pragma unroll
    for (int i = 0; i < 4; i++)
        #pragma unroll
        for (int j = 0; j < 4; j++)
            #pragma unroll
            for (int e = 0; e < 4; e++) acc[i][j][e] = 0.f;

    const int NC = K >> 5;          // K / 32

    // Always commits exactly one group (empty if cidx >= NC).
    #define PREFETCH(cidx, stage) do {                                         \
        if ((cidx) < NC) {                                                     \
            const int _k0 = (cidx) << 5;                                       \
            uint32_t _sb = sbase + (stage) * 2 * BUF_BYTES;                    \
            _Pragma("unroll")                                                  \
            for (int _half = 0; _half < 2; _half++) {                          \
                int _row = rowc + _half * 64;                                  \
                _Pragma("unroll")                                              \
                for (int _cc = 0; _cc < 2; _cc++) {                            \
                    int _ch = cbase + _cc * 4;                                 \
                    uint32_t _o = (uint32_t)(_row * LDKF + _ch * 4) * 4;       \
                    CP_ASYNC16(_sb + _o,                                       \
                               A + (size_t)(m0 + _row) * K + _k0 + _ch * 4);   \
                    CP_ASYNC16(_sb + BUF_BYTES + _o,                           \
                               B + (size_t)(n0 + _row) * K + _k0 + _ch * 4);   \
                }                                                              \
            }                                                                  \
        }                                                                      \
        CP_COMMIT();                                                           \
    } while (0)

    PREFETCH(0, 0);
    PREFETCH(1, 1);

    for (int c = 0; c < NC; c++) {
        const int st = c % 3;
        CP_WAIT(1);
        __syncthreads();
        // stage (c+2)%3 == (c-1)%3: its readers finished before this barrier
        PREFETCH(c + 2, (c + 2) % 3);

        const uint32_t sA = sbase + (st * 2 + 0) * BUF_BYTES;
        const uint32_t sB = sbase + (st * 2 + 1) * BUF_BYTES;

        #pragma unroll
        for (int ks = 0; ks < 4; ks++) {        // 4 k-steps of 8
            uint32_t bh[4][2];
            #pragma unroll
            for (int pr = 0; pr < 2; pr++) {    // nf pairs {0,1}, {2,3}
                const uint32_t bo = boff + (pr * 16 * LDKF + ks * 8) * 4;
                LDM_X4(bh[pr*2][0], bh[pr*2][1], bh[pr*2+1][0], bh[pr*2+1][1],
                       sB + bo);
            }
            #pragma unroll
            for (int mf = 0; mf < 4; mf++) {
                uint32_t a[4];
                const uint32_t ao = aoff + (mf * 16 * LDKF + ks * 8) * 4;
                LDM_X4(a[0], a[1], a[2], a[3], sA + ao);
                #pragma unroll
                for (int nf = 0; nf < 4; nf++)
                    mma16808(acc[mf][nf], a[0], a[1], a[2], a[3],
                             bh[nf][0], bh[nf][1]);
            }
        }
    }
    #undef PREFETCH

    // ---- epilogue ----
    #pragma unroll
    for (int mf = 0; mf < 4; mf++) {
        const int ra = m0 + wm * 64 + mf * 16 + g;
        #pragma unroll
        for (int nf = 0; nf < 4; nf++) {
            const int col = n0 + wn * 32 + nf * 8 + tg * 2;
            const float b0 = bias[col], b1 = bias[col + 1];
            #pragma unroll
            for (int half = 0; half < 2; half++) {
                const int r = ra + half * 8;
                const float v0 = acc[mf][nf][half * 2 + 0] + b0;
                const float v1 = acc[mf][nf][half * 2 + 1] + b1;
                if (GELU) {
                    float g0 = 0.5f * v0 * (1.0f + erff(v0 * 0.70710678118654752f));
                    float g1 = 0.5f * v1 * (1.0f + erff(v1 * 0.70710678118654752f));
                    float2 o = make_float2(tf32r(g0), tf32r(g1));
                    *(float2*)&Of[(size_t)r * N + col] = o;
                } else {
                    const float2 rr = *(const float2*)&res[(size_t)r * N + col];
                    float2 o = make_float2(v0 + rr.x, v1 + rr.y);
                    *(float2*)&Of[(size_t)r * N + col] = o;
                }
            }
        }
    }
}

// ---------------- launch ----------------------------------------------------
extern "C" void kernel_launch(void* const* d_in, const int* in_sizes, int n_in,
                              void* d_out, int out_size) {
    const float* x   = (const float*)d_in[0];
    const float* w1  = (const float*)d_in[1];
    const float* b1  = (const float*)d_in[2];
    const float* w2  = (const float*)d_in[3];
    const float* b2  = (const float*)d_in[4];
    const float* g1  = (const float*)d_in[5];
    const float* be1 = (const float*)d_in[6];
    const float* g2  = (const float*)d_in[7];
    const float* be2 = (const float*)d_in[8];
    float* out = (float*)d_out;

    float *fr, *fi, *h, *act, *w1t, *w2t;
    cudaGetSymbolAddress((void**)&fr,  g_fr);
    cudaGetSymbolAddress((void**)&fi,  g_fi);
    cudaGetSymbolAddress((void**)&h,   g_h);
    cudaGetSymbolAddress((void**)&act, g_act);
    cudaGetSymbolAddress((void**)&w1t, g_w1t);
    cudaGetSymbolAddress((void**)&w2t, g_w2t);

    // tf32-rounded h lives in g_fi (dead after LN1 consumes fft imag part;
    // GEMM2 overwrites it with y only after GEMM1 consumed it)
    float* hr = fi;

    cudaFuncSetAttribute(tf32_gemm_kernel<0>,
                         cudaFuncAttributeMaxDynamicSharedMemorySize, GEMM_SMEM);
    cudaFuncSetAttribute(tf32_gemm_kernel<1>,
                         cudaFuncAttributeMaxDynamicSharedMemorySize, GEMM_SMEM);
    cudaFuncSetAttribute(fft_seq_kernel,
                         cudaFuncAttributeMaxDynamicSharedMemorySize, SEQ_SMEM);

    // 1. twiddles + weight prep (transpose + tf32 round)
    twiddle_init_kernel<<<8, 256>>>();
    transpose_round_kernel<<<dim3(FF / 32, HID / 32), dim3(32, 8)>>>(w1, w1t, HID, FF);
    transpose_round_kernel<<<dim3(HID / 32, FF / 32), dim3(32, 8)>>>(w2, w2t, FF, HID);
    // 2. FFT over hidden dim -> (g_fr, g_fi)
    fft_hidden_kernel<<<NROWS, 256>>>(x);
    // 3. FFT over seq dim (4 columns/block), real part -> g_fr (= x_ft)
    fft_seq_kernel<<<BATCH * HID / 4, 512, SEQ_SMEM>>>();
    // 4. h = LN1(x + x_ft) exact -> g_h, tf32-rounded copy -> g_fi
    add_ln_kernel<<<NROWS, 256>>>(x, fr, g1, be1, h, hr);
    // 5. act = tf32r(gelu(hr @ w1t + b1))
    tf32_gemm_kernel<1><<<dim3(FF / 128, NROWS / 128), 256, GEMM_SMEM>>>(
        hr, w1t, b1, nullptr, act, NROWS, FF, HID);
    // 6. y = act @ w2t + b2 + h -> g_fi (overwrites dead hr)
    tf32_gemm_kernel<0><<<dim3(HID / 128, NROWS / 128), 256, GEMM_SMEM>>>(
        act, w2t, b2, h, fi, NROWS, HID, FF);
    // 7. out = LN2(y)
    add_ln_kernel<<<NROWS, 256>>>(fi, nullptr, g2, be2, out, nullptr);
}